// round 8
// baseline (speedup 1.0000x reference)
#include <cuda_runtime.h>
#include <cuda_bf16.h>
#include <cstdint>

// Problem constants: N=50000, E=600000, D=128, NF=3, V=8
#define D_DIM 128
#define NF_DIM 3
#define V_DIM 8
#define MAX_N 50048

// Scratch (device globals; no allocation allowed)
__device__ float g_acc[MAX_N * D_DIM];   // neighbor message sums (zeroed each call)
__device__ float g_deg[MAX_N];           // in-degree (zeroed each call)

// ---------------------------------------------------------------------------
// K1: edge scatter. One warp per edge; lane owns 4 contiguous dims.
// ---------------------------------------------------------------------------
__global__ void edge_scatter_kernel(const float* __restrict__ nfeat,
                                    const int* __restrict__ src,
                                    const int* __restrict__ dst,
                                    const int* __restrict__ eidx,
                                    const float* __restrict__ emb,
                                    int E) {
    int e = blockIdx.x * (blockDim.x >> 5) + (threadIdx.x >> 5);
    if (e >= E) return;
    int lane = threadIdx.x & 31;

    int s  = __ldg(src + e);
    int d  = __ldg(dst + e);
    int i0 = __ldg(eidx + e * NF_DIM + 0);
    int i1 = __ldg(eidx + e * NF_DIM + 1);
    int i2 = __ldg(eidx + e * NF_DIM + 2);

    int c = lane * 4;
    float4 v  = __ldg(reinterpret_cast<const float4*>(nfeat + (size_t)s * D_DIM + c));
    float4 e0 = __ldg(reinterpret_cast<const float4*>(emb + ((0 * V_DIM + i0) * D_DIM) + c));
    float4 e1 = __ldg(reinterpret_cast<const float4*>(emb + ((1 * V_DIM + i1) * D_DIM) + c));
    float4 e2 = __ldg(reinterpret_cast<const float4*>(emb + ((2 * V_DIM + i2) * D_DIM) + c));

    float mx = v.x + e0.x + e1.x + e2.x;
    float my = v.y + e0.y + e1.y + e2.y;
    float mz = v.z + e0.z + e1.z + e2.z;
    float mw = v.w + e0.w + e1.w + e2.w;

    float* p = g_acc + (size_t)d * D_DIM + c;
    asm volatile("red.global.add.v4.f32 [%0], {%1, %2, %3, %4};"
                 :: "l"(p), "f"(mx), "f"(my), "f"(mz), "f"(mw) : "memory");

    if (lane == 0) {
        atomicAdd(&g_deg[d], 1.0f);
    }
}

// ---------------------------------------------------------------------------
// K2: PERSISTENT bf16x3 GEMM, 2 CTAs/SM. grid=296 x 256 threads (8 warps).
//     Tile: 64 rows x 128 cols. Warp tile 32x32 (warp grid 2x4).
//     out = ((nfeat + g_acc) / (g_deg + 1)) @ W + b
//     Smem (packed bf16 pairs in 32-bit words, row stride 68 words):
//       Wth[128][68], Wtl[128][68] (W transposed [n][k]), Hh[64][68], Hl[64][68]
//     ~105 KB per CTA -> 2 CTAs per SM for cross-CTA latency hiding.
// ---------------------------------------------------------------------------
#define SBW 68  // 32-bit words per smem row

__device__ __forceinline__ uint32_t pack_bf2(float a, float b) {
    __nv_bfloat162 h = __floats2bfloat162_rn(a, b);
    return *reinterpret_cast<uint32_t*>(&h);
}

__global__ void __launch_bounds__(256, 2)
gemm_bf16_kernel(const float* __restrict__ nfeat,
                 const float* __restrict__ W,
                 const float* __restrict__ b,
                 float* __restrict__ out, int N, int numTiles) {
    extern __shared__ uint32_t smu[];
    uint32_t* Wth = smu;                  // 128*68 words
    uint32_t* Wtl = Wth + D_DIM * SBW;    // 128*68 words
    uint32_t* Hh  = Wtl + D_DIM * SBW;    // 64*68 words
    uint32_t* Hl  = Hh + 64 * SBW;        // 64*68 words
    float* bs = reinterpret_cast<float*>(Hl + 64 * SBW);  // 128 floats

    int tid = threadIdx.x;

    // Stage W transposed, split into bf16 hi/lo (once per persistent block)
    {
        __nv_bfloat16* Wth_b = reinterpret_cast<__nv_bfloat16*>(Wth);
        __nv_bfloat16* Wtl_b = reinterpret_cast<__nv_bfloat16*>(Wtl);
        const float4* W4 = reinterpret_cast<const float4*>(W);
        for (int i = tid; i < (D_DIM * D_DIM) / 4; i += 256) {
            int k = i >> 5;
            int n4 = (i & 31) * 4;
            float4 w = __ldg(W4 + i);
            #pragma unroll
            for (int j = 0; j < 4; j++) {
                float x = (&w.x)[j];
                __nv_bfloat16 hb = __float2bfloat16_rn(x);
                __nv_bfloat16 lb = __float2bfloat16_rn(x - __bfloat162float(hb));
                Wth_b[(n4 + j) * (2 * SBW) + k] = hb;
                Wtl_b[(n4 + j) * (2 * SBW) + k] = lb;
            }
        }
        if (tid < D_DIM) bs[tid] = __ldg(b + tid);
    }

    int wid = tid >> 5;
    int lane = tid & 31;
    int gid = lane >> 2;        // 0..7
    int tig = lane & 3;         // 0..3
    int wr = (wid >> 2) * 32;   // warp row base 0/32
    int wc = (wid & 3) * 32;    // warp col base 0/32/64/96

    const float4* nf4 = reinterpret_cast<const float4*>(nfeat);
    const float4* ac4 = reinterpret_cast<const float4*>(g_acc);

    for (int tile = blockIdx.x; tile < numTiles; tile += gridDim.x) {
        int row0 = tile * 64;

        __syncthreads();  // previous tile's MMA reads done before Hh/Hl overwrite

        // Stage H (64 rows): h = (nfeat + acc) / (deg + 1), split bf16 hi/lo
        for (int i = tid; i < 64 * 32; i += 256) {
            int lr = i >> 5;
            int c4 = i & 31;
            int row = row0 + lr;
            float4 v = make_float4(0.f, 0.f, 0.f, 0.f);
            if (row < N) {
                float4 nv = __ldg(nf4 + (size_t)row * 32 + c4);
                float4 av = *(ac4 + (size_t)row * 32 + c4);
                float invd = 1.0f / (g_deg[row] + 1.0f);
                v = make_float4((nv.x + av.x) * invd, (nv.y + av.y) * invd,
                                (nv.z + av.z) * invd, (nv.w + av.w) * invd);
            }
            __nv_bfloat16 hx = __float2bfloat16_rn(v.x);
            __nv_bfloat16 hy = __float2bfloat16_rn(v.y);
            __nv_bfloat16 hz = __float2bfloat16_rn(v.z);
            __nv_bfloat16 hw = __float2bfloat16_rn(v.w);
            int base = lr * SBW + c4 * 2;
            Hh[base]     = pack_bf2(__bfloat162float(hx), __bfloat162float(hy));
            Hh[base + 1] = pack_bf2(__bfloat162float(hz), __bfloat162float(hw));
            Hl[base]     = pack_bf2(v.x - __bfloat162float(hx), v.y - __bfloat162float(hy));
            Hl[base + 1] = pack_bf2(v.z - __bfloat162float(hz), v.w - __bfloat162float(hw));
        }
        __syncthreads();

        float c[2][4][4];
        #pragma unroll
        for (int mt = 0; mt < 2; mt++)
            #pragma unroll
            for (int nt = 0; nt < 4; nt++)
                #pragma unroll
                for (int r = 0; r < 4; r++) c[mt][nt][r] = 0.f;

        #pragma unroll
        for (int kw = 0; kw < 64; kw += 8) {   // kw = k/2 (word index); K chunk = 16
            uint32_t ah[2][4], al[2][4];
            #pragma unroll
            for (int mt = 0; mt < 2; mt++) {
                int r = wr + mt * 16 + gid;
                ah[mt][0] = Hh[r * SBW + kw + tig];
                ah[mt][1] = Hh[(r + 8) * SBW + kw + tig];
                ah[mt][2] = Hh[r * SBW + kw + 4 + tig];
                ah[mt][3] = Hh[(r + 8) * SBW + kw + 4 + tig];
                al[mt][0] = Hl[r * SBW + kw + tig];
                al[mt][1] = Hl[(r + 8) * SBW + kw + tig];
                al[mt][2] = Hl[r * SBW + kw + 4 + tig];
                al[mt][3] = Hl[(r + 8) * SBW + kw + 4 + tig];
            }
            uint32_t bh[4][2], bl[4][2];
            #pragma unroll
            for (int nt = 0; nt < 4; nt++) {
                int n = wc + nt * 8 + gid;
                bh[nt][0] = Wth[n * SBW + kw + tig];
                bh[nt][1] = Wth[n * SBW + kw + 4 + tig];
                bl[nt][0] = Wtl[n * SBW + kw + tig];
                bl[nt][1] = Wtl[n * SBW + kw + 4 + tig];
            }
            #pragma unroll
            for (int mt = 0; mt < 2; mt++) {
                #pragma unroll
                for (int nt = 0; nt < 4; nt++) {
                    #define MMA16(A, B)                                                  \
                        asm volatile(                                                    \
                            "mma.sync.aligned.m16n8k16.row.col.f32.bf16.bf16.f32 "       \
                            "{%0,%1,%2,%3}, {%4,%5,%6,%7}, {%8,%9}, {%0,%1,%2,%3};"      \
                            : "+f"(c[mt][nt][0]), "+f"(c[mt][nt][1]),                    \
                              "+f"(c[mt][nt][2]), "+f"(c[mt][nt][3])                     \
                            : "r"(A[0]), "r"(A[1]), "r"(A[2]), "r"(A[3]),                \
                              "r"(B[0]), "r"(B[1]))
                    MMA16(ah[mt], bh[nt]);
                    MMA16(al[mt], bh[nt]);
                    MMA16(ah[mt], bl[nt]);
                    #undef MMA16
                }
            }
        }

        // Epilogue: add bias, store
        #pragma unroll
        for (int mt = 0; mt < 2; mt++) {
            #pragma unroll
            for (int nt = 0; nt < 4; nt++) {
                int col = wc + nt * 8 + 2 * tig;
                float bx = bs[col], by = bs[col + 1];
                int r_top = row0 + wr + mt * 16 + gid;
                if (r_top < N) {
                    float2 o = make_float2(c[mt][nt][0] + bx, c[mt][nt][1] + by);
                    *reinterpret_cast<float2*>(out + (size_t)r_top * D_DIM + col) = o;
                }
                int r_bot = r_top + 8;
                if (r_bot < N) {
                    float2 o = make_float2(c[mt][nt][2] + bx, c[mt][nt][3] + by);
                    *reinterpret_cast<float2*>(out + (size_t)r_bot * D_DIM + col) = o;
                }
            }
        }
    }
}

// ---------------------------------------------------------------------------
// Launch
// Inputs: nfeat[N*D] f32, src[E] i32, dst[E] i32, efeat_idx[E*3] i32,
//         edge_emb[3*8*128] f32, W[128*128] f32, b[128] f32 -> out float[N*128]
// ---------------------------------------------------------------------------
extern "C" void kernel_launch(void* const* d_in, const int* in_sizes, int n_in,
                              void* d_out, int out_size) {
    const float* nfeat = (const float*)d_in[0];
    const int*   src   = (const int*)d_in[1];
    const int*   dst   = (const int*)d_in[2];
    const int*   eidx  = (const int*)d_in[3];
    const float* emb   = (const float*)d_in[4];
    const float* W     = (const float*)d_in[5];
    const float* b     = (const float*)d_in[6];
    float* out = (float*)d_out;

    int N = in_sizes[0] / D_DIM;
    int E = in_sizes[1];

    // Zero accumulators (graph-capturable async memsets)
    void* acc_ptr = nullptr;
    void* deg_ptr = nullptr;
    cudaGetSymbolAddress(&acc_ptr, g_acc);
    cudaGetSymbolAddress(&deg_ptr, g_deg);
    cudaMemsetAsync(acc_ptr, 0, (size_t)N * D_DIM * sizeof(float));
    cudaMemsetAsync(deg_ptr, 0, (size_t)N * sizeof(float));

    // Edge scatter: 8 edges per 256-thread block
    edge_scatter_kernel<<<(E + 7) / 8, 256>>>(nfeat, src, dst, eidx, emb, E);

    // Persistent bf16x3 GEMM, 2 CTAs/SM (64-row tiles)
    int numTiles = (N + 63) / 64;
    int smem = (2 * D_DIM * SBW + 2 * 64 * SBW + 128) * 4;  // 104,960 B
    cudaFuncSetAttribute(gemm_bf16_kernel, cudaFuncAttributeMaxDynamicSharedMemorySize, smem);
    gemm_bf16_kernel<<<296, 256, smem>>>(nfeat, W, b, out, N, numTiles);
}

// round 9
// speedup vs baseline: 1.0368x; 1.0368x over previous
#include <cuda_runtime.h>
#include <cuda_bf16.h>
#include <cstdint>

// Problem constants: N=50000, E=600000, D=128, NF=3, V=8
#define D_DIM 128
#define NF_DIM 3
#define V_DIM 8
#define MAX_N 50048
#define SBW 68  // 32-bit words per smem row (136 bf16)

// Scratch (device globals; no allocation allowed)
__device__ float g_acc[MAX_N * D_DIM];            // neighbor message sums
__device__ float g_deg[MAX_N];                    // in-degree
__device__ uint32_t g_Wpk[2 * D_DIM * SBW];       // packed W: [Wth | Wtl], smem-ready layout

// ---------------------------------------------------------------------------
// K0: pack W -> [Wth | Wtl] in final smem word layout.
//     Wth word[n*SBW + k/2] = (bf16(W[k][n]), bf16(W[k+1][n]))  (lo=k, hi=k+1)
//     Wtl analogous with residuals.
// ---------------------------------------------------------------------------
__global__ void wsplit_kernel(const float* __restrict__ W) {
    int i = blockIdx.x * blockDim.x + threadIdx.x;   // (n, kpair)
    if (i >= D_DIM * (D_DIM / 2)) return;
    int n = i >> 6;
    int kp = i & 63;
    int k = kp * 2;
    float x0 = __ldg(W + k * D_DIM + n);
    float x1 = __ldg(W + (k + 1) * D_DIM + n);
    __nv_bfloat16 h0 = __float2bfloat16_rn(x0);
    __nv_bfloat16 h1 = __float2bfloat16_rn(x1);
    __nv_bfloat16 l0 = __float2bfloat16_rn(x0 - __bfloat162float(h0));
    __nv_bfloat16 l1 = __float2bfloat16_rn(x1 - __bfloat162float(h1));
    __nv_bfloat162 hp = __nv_bfloat162(h0, h1);
    __nv_bfloat162 lp = __nv_bfloat162(l0, l1);
    g_Wpk[n * SBW + kp]                  = *reinterpret_cast<uint32_t*>(&hp);
    g_Wpk[D_DIM * SBW + n * SBW + kp]    = *reinterpret_cast<uint32_t*>(&lp);
}

// ---------------------------------------------------------------------------
// K1: edge scatter. One warp per edge; lane owns 4 contiguous dims.
// ---------------------------------------------------------------------------
__global__ void edge_scatter_kernel(const float* __restrict__ nfeat,
                                    const int* __restrict__ src,
                                    const int* __restrict__ dst,
                                    const int* __restrict__ eidx,
                                    const float* __restrict__ emb,
                                    int E) {
    int e = blockIdx.x * (blockDim.x >> 5) + (threadIdx.x >> 5);
    if (e >= E) return;
    int lane = threadIdx.x & 31;

    int s  = __ldg(src + e);
    int d  = __ldg(dst + e);
    int i0 = __ldg(eidx + e * NF_DIM + 0);
    int i1 = __ldg(eidx + e * NF_DIM + 1);
    int i2 = __ldg(eidx + e * NF_DIM + 2);

    int c = lane * 4;
    float4 v  = __ldg(reinterpret_cast<const float4*>(nfeat + (size_t)s * D_DIM + c));
    float4 e0 = __ldg(reinterpret_cast<const float4*>(emb + ((0 * V_DIM + i0) * D_DIM) + c));
    float4 e1 = __ldg(reinterpret_cast<const float4*>(emb + ((1 * V_DIM + i1) * D_DIM) + c));
    float4 e2 = __ldg(reinterpret_cast<const float4*>(emb + ((2 * V_DIM + i2) * D_DIM) + c));

    float mx = v.x + e0.x + e1.x + e2.x;
    float my = v.y + e0.y + e1.y + e2.y;
    float mz = v.z + e0.z + e1.z + e2.z;
    float mw = v.w + e0.w + e1.w + e2.w;

    float* p = g_acc + (size_t)d * D_DIM + c;
    asm volatile("red.global.add.v4.f32 [%0], {%1, %2, %3, %4};"
                 :: "l"(p), "f"(mx), "f"(my), "f"(mz), "f"(mw) : "memory");

    if (lane == 0) {
        atomicAdd(&g_deg[d], 1.0f);
    }
}

// ---------------------------------------------------------------------------
// K2: NON-PERSISTENT bf16x3 GEMM, one 64x128 tile per block, 2 CTAs/SM.
//     256 threads = 8 warps, warp grid 2x4, warp tile 32x32.
//     out = ((nfeat + g_acc) / (g_deg + 1)) @ W + b
//     W staging = pure uint4 copy of g_Wpk (pre-packed). Cross-phase overlap
//     comes from co-resident CTAs at different phases.
// ---------------------------------------------------------------------------
__device__ __forceinline__ uint32_t pack_bf2(float a, float b) {
    __nv_bfloat162 h = __floats2bfloat162_rn(a, b);
    return *reinterpret_cast<uint32_t*>(&h);
}

__global__ void __launch_bounds__(256, 2)
gemm_bf16_kernel(const float* __restrict__ nfeat,
                 const float* __restrict__ b,
                 float* __restrict__ out, int N) {
    extern __shared__ uint32_t smu[];
    uint32_t* Wth = smu;                  // 128*68 words
    uint32_t* Wtl = Wth + D_DIM * SBW;    // 128*68 words
    uint32_t* Hh  = Wtl + D_DIM * SBW;    // 64*68 words
    uint32_t* Hl  = Hh + 64 * SBW;        // 64*68 words
    float* bs = reinterpret_cast<float*>(Hl + 64 * SBW);  // 128 floats

    int tid = threadIdx.x;
    int row0 = blockIdx.x * 64;

    // Stage W: straight contiguous copy (both halves at once)
    {
        const uint4* src4 = reinterpret_cast<const uint4*>(g_Wpk);
        uint4* dst4 = reinterpret_cast<uint4*>(smu);
        #pragma unroll
        for (int i = tid; i < (2 * D_DIM * SBW) / 4; i += 256)
            dst4[i] = src4[i];
        if (tid < D_DIM) bs[tid] = __ldg(b + tid);
    }

    // Stage H (64 rows): h = (nfeat + acc) / (deg + 1), split bf16 hi/lo
    {
        const float4* nf4 = reinterpret_cast<const float4*>(nfeat);
        const float4* ac4 = reinterpret_cast<const float4*>(g_acc);
        for (int i = tid; i < 64 * 32; i += 256) {
            int lr = i >> 5;
            int c4 = i & 31;
            int row = row0 + lr;
            float4 v = make_float4(0.f, 0.f, 0.f, 0.f);
            if (row < N) {
                float4 nv = __ldg(nf4 + (size_t)row * 32 + c4);
                float4 av = *(ac4 + (size_t)row * 32 + c4);
                float invd = 1.0f / (g_deg[row] + 1.0f);
                v = make_float4((nv.x + av.x) * invd, (nv.y + av.y) * invd,
                                (nv.z + av.z) * invd, (nv.w + av.w) * invd);
            }
            __nv_bfloat16 hx = __float2bfloat16_rn(v.x);
            __nv_bfloat16 hy = __float2bfloat16_rn(v.y);
            __nv_bfloat16 hz = __float2bfloat16_rn(v.z);
            __nv_bfloat16 hw = __float2bfloat16_rn(v.w);
            int base = lr * SBW + c4 * 2;
            Hh[base]     = pack_bf2(__bfloat162float(hx), __bfloat162float(hy));
            Hh[base + 1] = pack_bf2(__bfloat162float(hz), __bfloat162float(hw));
            Hl[base]     = pack_bf2(v.x - __bfloat162float(hx), v.y - __bfloat162float(hy));
            Hl[base + 1] = pack_bf2(v.z - __bfloat162float(hz), v.w - __bfloat162float(hw));
        }
    }
    __syncthreads();

    int wid = tid >> 5;
    int lane = tid & 31;
    int gid = lane >> 2;
    int tig = lane & 3;
    int wr = (wid >> 2) * 32;   // 0/32
    int wc = (wid & 3) * 32;    // 0/32/64/96

    float c[2][4][4];
    #pragma unroll
    for (int mt = 0; mt < 2; mt++)
        #pragma unroll
        for (int nt = 0; nt < 4; nt++)
            #pragma unroll
            for (int r = 0; r < 4; r++) c[mt][nt][r] = 0.f;

    #pragma unroll
    for (int kw = 0; kw < 64; kw += 8) {   // K chunk = 16
        uint32_t ah[2][4], al[2][4];
        #pragma unroll
        for (int mt = 0; mt < 2; mt++) {
            int r = wr + mt * 16 + gid;
            ah[mt][0] = Hh[r * SBW + kw + tig];
            ah[mt][1] = Hh[(r + 8) * SBW + kw + tig];
            ah[mt][2] = Hh[r * SBW + kw + 4 + tig];
            ah[mt][3] = Hh[(r + 8) * SBW + kw + 4 + tig];
            al[mt][0] = Hl[r * SBW + kw + tig];
            al[mt][1] = Hl[(r + 8) * SBW + kw + tig];
            al[mt][2] = Hl[r * SBW + kw + 4 + tig];
            al[mt][3] = Hl[(r + 8) * SBW + kw + 4 + tig];
        }
        uint32_t bh[4][2], bl[4][2];
        #pragma unroll
        for (int nt = 0; nt < 4; nt++) {
            int n = wc + nt * 8 + gid;
            bh[nt][0] = Wth[n * SBW + kw + tig];
            bh[nt][1] = Wth[n * SBW + kw + 4 + tig];
            bl[nt][0] = Wtl[n * SBW + kw + tig];
            bl[nt][1] = Wtl[n * SBW + kw + 4 + tig];
        }
        #pragma unroll
        for (int mt = 0; mt < 2; mt++) {
            #pragma unroll
            for (int nt = 0; nt < 4; nt++) {
                #define MMA16(A, B)                                                  \
                    asm volatile(                                                    \
                        "mma.sync.aligned.m16n8k16.row.col.f32.bf16.bf16.f32 "       \
                        "{%0,%1,%2,%3}, {%4,%5,%6,%7}, {%8,%9}, {%0,%1,%2,%3};"      \
                        : "+f"(c[mt][nt][0]), "+f"(c[mt][nt][1]),                    \
                          "+f"(c[mt][nt][2]), "+f"(c[mt][nt][3])                     \
                        : "r"(A[0]), "r"(A[1]), "r"(A[2]), "r"(A[3]),                \
                          "r"(B[0]), "r"(B[1]))
                MMA16(ah[mt], bh[nt]);
                MMA16(al[mt], bh[nt]);
                MMA16(ah[mt], bl[nt]);
                #undef MMA16
            }
        }
    }

    // Epilogue: add bias, store
    #pragma unroll
    for (int mt = 0; mt < 2; mt++) {
        #pragma unroll
        for (int nt = 0; nt < 4; nt++) {
            int col = wc + nt * 8 + 2 * tig;
            float bx = bs[col], by = bs[col + 1];
            int r_top = row0 + wr + mt * 16 + gid;
            if (r_top < N) {
                float2 o = make_float2(c[mt][nt][0] + bx, c[mt][nt][1] + by);
                *reinterpret_cast<float2*>(out + (size_t)r_top * D_DIM + col) = o;
            }
            int r_bot = r_top + 8;
            if (r_bot < N) {
                float2 o = make_float2(c[mt][nt][2] + bx, c[mt][nt][3] + by);
                *reinterpret_cast<float2*>(out + (size_t)r_bot * D_DIM + col) = o;
            }
        }
    }
}

// ---------------------------------------------------------------------------
// Launch
// Inputs: nfeat[N*D] f32, src[E] i32, dst[E] i32, efeat_idx[E*3] i32,
//         edge_emb[3*8*128] f32, W[128*128] f32, b[128] f32 -> out float[N*128]
// ---------------------------------------------------------------------------
extern "C" void kernel_launch(void* const* d_in, const int* in_sizes, int n_in,
                              void* d_out, int out_size) {
    const float* nfeat = (const float*)d_in[0];
    const int*   src   = (const int*)d_in[1];
    const int*   dst   = (const int*)d_in[2];
    const int*   eidx  = (const int*)d_in[3];
    const float* emb   = (const float*)d_in[4];
    const float* W     = (const float*)d_in[5];
    const float* b     = (const float*)d_in[6];
    float* out = (float*)d_out;

    int N = in_sizes[0] / D_DIM;
    int E = in_sizes[1];

    // Zero accumulators (graph-capturable async memsets)
    void* acc_ptr = nullptr;
    void* deg_ptr = nullptr;
    cudaGetSymbolAddress(&acc_ptr, g_acc);
    cudaGetSymbolAddress(&deg_ptr, g_deg);
    cudaMemsetAsync(acc_ptr, 0, (size_t)N * D_DIM * sizeof(float));
    cudaMemsetAsync(deg_ptr, 0, (size_t)N * sizeof(float));

    // Pack W once (8192 threads)
    wsplit_kernel<<<32, 256>>>(W);

    // Edge scatter: 8 edges per 256-thread block
    edge_scatter_kernel<<<(E + 7) / 8, 256>>>(nfeat, src, dst, eidx, emb, E);

    // Non-persistent GEMM: one 64-row tile per block, 2 CTAs/SM
    int numTiles = (N + 63) / 64;
    int smem = (2 * D_DIM * SBW + 2 * 64 * SBW + 128) * 4;  // 104,960 B
    cudaFuncSetAttribute(gemm_bf16_kernel, cudaFuncAttributeMaxDynamicSharedMemorySize, smem);
    gemm_bf16_kernel<<<numTiles, 256, smem>>>(nfeat, b, out, N);
}